// round 4
// baseline (speedup 1.0000x reference)
#include <cuda_runtime.h>
#include <cuda_bf16.h>

#define NT 2000
#define NS 2048
#define NH 16
#define PF 4   // prefetch depth (NT % PF == 0)

__device__ __forceinline__ float sigmoidf_(float x) {
    return 1.0f / (1.0f + expf(-x));
}

// Guarded streaming load: cannot fault if p is valid for n elements.
__device__ __forceinline__ float gld(const float* __restrict__ p, long long idx, long long n) {
    return (idx < n) ? __ldcs(p + idx) : 0.0f;
}

template <bool FULL_OUT>
__global__ __launch_bounds__(128)
void waternet_kernel(const float* __restrict__ P, const float* __restrict__ T,
                     const float* __restrict__ E,
                     const float* __restrict__ w_o, const float* __restrict__ wF,
                     const float* __restrict__ wG, const float* __restrict__ wl,
                     const float* __restrict__ we, const float* __restrict__ wk,
                     const float* __restrict__ ws,
                     float* __restrict__ out,
                     long long pn, long long tn, long long en, long long wn,
                     long long out_elems)
{
    const int t = blockIdx.x * blockDim.x + threadIdx.x;
    const int s = t >> 4;      // site
    const int h = t & 15;      // head
    if (s >= NS) return;

    const long long QN = (long long)NT * NS;       //  4,096,000
    const long long FN = QN * NH;                  // 65,536,000
    const long long Fbase = QN;
    const long long Hbase = QN + FN;
    const long long Gbase = QN + 2 * FN;

    // ---- per-head constants (all weight reads guarded by wn) ----
    float ssum = 0.0f;
    #pragma unroll
    for (int i = 0; i < NH; i++) ssum += (i < wn) ? expf(w_o[i]) : 0.0f;
    const bool hw = (h < wn);
    const float a    = (hw ? expf(w_o[h]) : 0.0f) / ssum;
    const float melt = (hw ? expf(wF[h]) : 0.0f) + 1.0f;
    const float cap  = expf(2.0f * (hw ? wl[h] : 0.0f));
    const float swe  = sigmoidf_(hw ? we[h] : 0.0f);
    const float swk  = sigmoidf_(hw ? wk[h] : 0.0f);
    const float sws  = sigmoidf_(hw ? ws[h] : 0.0f);
    const float swg  = sigmoidf_(hw ? wG[h] : 0.0f);

    // ---- state carries ----
    float f = 0.0f, hs = 0.0f, g = 0.0f;

    // ---- prefetch ring (guarded loads) ----
    float pk[PF], tk[PF], ek[PF];
    #pragma unroll
    for (int i = 0; i < PF; i++) {
        const long long idx = (long long)i * NS + s;
        pk[i] = gld(P, idx, pn);
        tk[i] = gld(T, idx, tn);
        ek[i] = gld(E, idx, en);
    }

    const long long out_stride = (long long)NS * NH;
    long long oidx = (long long)s * NH + h;
    long long qidx = s;

    for (int k0 = 0; k0 < NT; k0 += PF) {
        #pragma unroll
        for (int j = 0; j < PF; j++) {
            const int k = k0 + j;
            const float Pk = pk[j], Tk = tk[j], Ek = ek[j];
            const int kn = k + PF;
            if (kn < NT) {
                const long long idx = (long long)kn * NS + s;
                pk[j] = gld(P, idx, pn);
                tk[j] = gld(T, idx, tn);
                ek[j] = gld(E, idx, en);
            }

            // SnowBucket
            const float sm    = fmaxf(Tk, 0.0f) * melt;
            const float m     = fminf(sm, f);
            const float pcold = (Tk < 0.0f) ? Pk : 0.0f;
            const float pwarm = (Tk > 0.0f) ? Pk : 0.0f;
            f = f - m + pcold;
            const float x = pwarm + m;

            // SoilBucket
            const float hn  = hs + x;
            const float h1  = fmaxf(hn - cap, 0.0f);
            const float q1  = fmaxf(h1 - Ek * swe, 0.0f);
            const float h2  = hn - h1;
            const float q2  = h2 * swk;
            hs = h2 - q2;
            const float q2a = q2 * sws;
            const float q2b = q2 - q2a;

            // LinearBucket (groundwater)
            const float q3 = (q2b + g) * swg;
            g = g - q3 + q2b;

            // state histories — every store doubly guarded
            if (FULL_OUT) {
                const long long fi = Fbase + oidx;
                const long long hi = Hbase + oidx;
                const long long gi = Gbase + oidx;
                if (fi < out_elems) __stcs(out + fi, f);
                if (hi < out_elems) __stcs(out + hi, hs);
                if (gi < out_elems) __stcs(out + gi, g);
            }

            // mixed discharge: reduce 16 heads within the warp half-group
            float qc = (q1 + q2a + q3) * a;
            qc += __shfl_xor_sync(0xffffffffu, qc, 8);
            qc += __shfl_xor_sync(0xffffffffu, qc, 4);
            qc += __shfl_xor_sync(0xffffffffu, qc, 2);
            qc += __shfl_xor_sync(0xffffffffu, qc, 1);
            if (h == 0 && qidx < out_elems && qidx < QN) __stcs(out + qidx, qc);

            oidx += out_stride;
            qidx += NS;
        }
    }
}

extern "C" void kernel_launch(void* const* d_in, const int* in_sizes, int n_in,
                              void* d_out, int out_size) {
    // Classify by threshold (robust to elements-vs-bytes):
    //   big  (>10000): P, T, E  (relative order preserved)
    //   small:         w_o, wF, wG, wl, we, wk, ws
    const long long QN = (long long)NT * NS;
    const float* big[3]    = {nullptr, nullptr, nullptr};
    long long     bigsz[3] = {0, 0, 0};
    const float* small7[7] = {nullptr, nullptr, nullptr, nullptr, nullptr, nullptr, nullptr};
    long long    smallsz[7]= {0, 0, 0, 0, 0, 0, 0};
    int nb = 0, nsml = 0;
    for (int i = 0; i < n_in; i++) {
        if (d_in[i] == nullptr) continue;                  // never keep null pointers
        const long long sz = (long long)in_sizes[i];
        if (sz > 10000) {
            if (nb < 3) { big[nb] = (const float*)d_in[i]; bigsz[nb] = sz; nb++; }
        } else if (sz > 0) {
            if (nsml < 7) { small7[nsml] = (const float*)d_in[i]; smallsz[nsml] = sz; nsml++; }
        }
    }
    if (nb < 3) return;  // unresolvable -> clean "no work" failure, not a crash

    const float* P = big[0]; const long long pn = bigsz[0];
    const float* T = big[1]; const long long tn = bigsz[1];
    const float* E = big[2]; const long long en = bigsz[2];

    const float *w_o, *wF, *wG, *wl, *we, *wk, *ws;
    long long wn = 0;
    if (nsml >= 7) {
        w_o = small7[0]; wF = small7[1]; wG = small7[2]; wl = small7[3];
        we  = small7[4]; wk = small7[5]; ws = small7[6];
        wn = smallsz[0];
        for (int i = 1; i < 7; i++) if (smallsz[i] < wn) wn = smallsz[i];
        if (wn > NH) wn = NH;
    } else if (nsml >= 1 && smallsz[0] >= 7 * NH) {
        // single packed blob: [w_o | wF | wG | wl | we | wk | ws]
        const float* base = small7[0];
        w_o = base;          wF = base + NH;     wG = base + 2 * NH;
        wl  = base + 3 * NH; we = base + 4 * NH; wk = base + 5 * NH;
        ws  = base + 6 * NH;
        wn = NH;
    } else {
        return;
    }
    if (!P || !T || !E || !w_o || !wF || !wG || !wl || !we || !wk || !ws) return;

    float* out = (float*)d_out;
    if (!out || out_size <= 0) return;
    const long long out_elems = (long long)out_size;
    const long long fullElems = QN + 3LL * QN * NH;  // Q + F + H + G = 200,704,000

    const int threads = 128;
    const int blocks  = (NS * NH + threads - 1) / threads;  // 256

    if (out_elems >= fullElems) {
        waternet_kernel<true><<<blocks, threads>>>(P, T, E, w_o, wF, wG, wl, we, wk, ws,
                                                   out, pn, tn, en, wn, out_elems);
    } else {
        waternet_kernel<false><<<blocks, threads>>>(P, T, E, w_o, wF, wG, wl, we, wk, ws,
                                                    out, pn, tn, en, wn, out_elems);
    }
}

// round 5
// speedup vs baseline: 3.6801x; 3.6801x over previous
#include <cuda_runtime.h>
#include <cuda_bf16.h>

#define NT 2000
#define NS 2048
#define NH 16
#define PF 16   // prefetch depth; NT % PF == 0 (2000 = 125*16)

__device__ __forceinline__ float sigmoidf_(float x) {
    return 1.0f / (1.0f + expf(-x));
}

__global__ __launch_bounds__(224, 1)
void waternet_kernel(const float* __restrict__ P, const float* __restrict__ T,
                     const float* __restrict__ E,
                     const float* __restrict__ w_o, const float* __restrict__ wF,
                     const float* __restrict__ wG, const float* __restrict__ wl,
                     const float* __restrict__ we, const float* __restrict__ wk,
                     const float* __restrict__ ws,
                     float* __restrict__ Qo, float* __restrict__ Fo,
                     float* __restrict__ Ho, float* __restrict__ Go)
{
    const unsigned t = blockIdx.x * blockDim.x + threadIdx.x;
    const unsigned s = t >> 4;      // site
    const unsigned h = t & 15;      // head
    if (s >= NS) return;

    // ---- per-head constants (once) ----
    float ssum = 0.0f;
    #pragma unroll
    for (int i = 0; i < NH; i++) ssum += expf(w_o[i]);
    const float a    = expf(w_o[h]) / ssum;       // softmax mixing weight
    const float melt = expf(wF[h]) + 1.0f;        // snow melt factor
    const float cap  = expf(2.0f * wl[h]);        // soil capacity
    const float swe  = sigmoidf_(we[h]);
    const float swk  = sigmoidf_(wk[h]);
    const float sws  = sigmoidf_(ws[h]);
    const float swg  = sigmoidf_(wG[h]);

    // ---- state carries ----
    float f = 0.0f, hs = 0.0f, g = 0.0f;

    // ---- deep prefetch ring: distance PF steps >> DRAM latency ----
    float pk[PF], tk[PF], ek[PF];
    #pragma unroll
    for (int i = 0; i < PF; i++) {
        const unsigned idx = (unsigned)i * NS + s;
        pk[i] = __ldg(P + idx);
        tk[i] = __ldg(T + idx);
        ek[i] = __ldg(E + idx);
    }

    const unsigned out_stride = NS * NH;          // 32768
    unsigned oidx = s * NH + h;                   // max ~65.5M, fits u32
    unsigned qidx = s;
    unsigned lidx = (unsigned)PF * NS + s;        // next load index

    for (int k0 = 0; k0 < NT; k0 += PF) {
        #pragma unroll
        for (int j = 0; j < PF; j++) {
            const float Pk = pk[j], Tk = tk[j], Ek = ek[j];
            // refill ring slot j with step k0+j+PF (guard only near the end)
            if (k0 + j + PF < NT) {
                pk[j] = __ldg(P + lidx);
                tk[j] = __ldg(T + lidx);
                ek[j] = __ldg(E + lidx);
            }
            lidx += NS;

            // SnowBucket
            const float sm    = fmaxf(Tk, 0.0f) * melt;
            const float m     = fminf(sm, f);
            const float pcold = (Tk < 0.0f) ? Pk : 0.0f;
            const float pwarm = (Tk > 0.0f) ? Pk : 0.0f;
            f = f - m + pcold;
            const float x = pwarm + m;

            // SoilBucket
            const float hn  = hs + x;
            const float h1  = fmaxf(hn - cap, 0.0f);
            const float q1  = fmaxf(h1 - Ek * swe, 0.0f);
            const float h2  = hn - h1;
            const float q2  = h2 * swk;
            hs = h2 - q2;
            const float q2a = q2 * sws;
            const float q2b = q2 - q2a;

            // LinearBucket (groundwater)
            const float q3 = (q2b + g) * swg;
            g = g - q3 + q2b;

            // state histories: streaming, fully coalesced per warp
            __stcs(Fo + oidx, f);
            __stcs(Ho + oidx, hs);
            __stcs(Go + oidx, g);

            // mixed discharge: butterfly over the aligned 16-lane head group
            float qc = (q1 + q2a + q3) * a;
            qc += __shfl_xor_sync(0xffffffffu, qc, 8);
            qc += __shfl_xor_sync(0xffffffffu, qc, 4);
            qc += __shfl_xor_sync(0xffffffffu, qc, 2);
            qc += __shfl_xor_sync(0xffffffffu, qc, 1);
            if (h == 0) __stcs(Qo + qidx, qc);

            oidx += out_stride;
            qidx += NS;
        }
    }
}

extern "C" void kernel_launch(void* const* d_in, const int* in_sizes, int n_in,
                              void* d_out, int out_size) {
    // Confirmed mapping (R4 passed, rel_err 1.4e-7):
    // big arrays in order: P, T, E; small in order: w_o, wF, wG, wl, we, wk, ws.
    const float* big[3]    = {nullptr, nullptr, nullptr};
    const float* small7[7] = {nullptr, nullptr, nullptr, nullptr, nullptr, nullptr, nullptr};
    int nb = 0, nsml = 0;
    for (int i = 0; i < n_in; i++) {
        if (d_in[i] == nullptr) continue;
        if (in_sizes[i] > 10000) {
            if (nb < 3) big[nb++] = (const float*)d_in[i];
        } else if (in_sizes[i] > 0) {
            if (nsml < 7) small7[nsml++] = (const float*)d_in[i];
        }
    }
    if (nb < 3 || nsml < 7) return;

    const float* P   = big[0];
    const float* T   = big[1];
    const float* E   = big[2];
    const float* w_o = small7[0];
    const float* wF  = small7[1];
    const float* wG  = small7[2];
    const float* wl  = small7[3];
    const float* we  = small7[4];
    const float* wk  = small7[5];
    const float* ws  = small7[6];

    float* out = (float*)d_out;
    const long long QN = (long long)NT * NS;
    // Layout confirmed: [Q (NT*NS) | F (NT*NS*NH) | H | G]
    float* Qo = out;
    float* Fo = Qo + QN;
    float* Ho = Fo + QN * NH;
    float* Go = Ho + QN * NH;

    // 148 blocks x 224 threads = 33152 >= 32768; one block per SM, perfect balance.
    const int threads = 224;
    const int blocks  = 148;
    waternet_kernel<<<blocks, threads>>>(P, T, E, w_o, wF, wG, wl, we, wk, ws,
                                         Qo, Fo, Ho, Go);
}